// round 9
// baseline (speedup 1.0000x reference)
#include <cuda_runtime.h>
#include <cuda_bf16.h>

#define FEAT 1024
#define NREF 4
#define WPB 8            // warps per block
#define TPB (WPB * 32)
#define GRID 296         // 2 CTAs/SM * 148 SMs, one wave, persistent

// Fused: per-block prologue (normalize v's + build compact-WY T), then
// persistent loop over row-pairs: d = Wᵀy (one dot pass, one butterfly),
// e = T d, y -= W e (one update pass).
__global__ __launch_bounds__(TPB, 2) void householder_wy_kernel(
    const float* __restrict__ x, const float* __restrict__ vecs,
    float* __restrict__ out, int batch) {
    __shared__ float sv[NREF][FEAT];     // normalized vectors
    __shared__ float s_nred[NREF][WPB];  // norm partials per warp
    __shared__ float s_gred[WPB][6];     // pairwise-dot partials per warp
    __shared__ float s_inv[NREF];
    __shared__ float s_T[16];

    int tid = threadIdx.x;
    int warp = tid >> 5;
    int lane = tid & 31;

    // ---- Prologue: every block computes identical normalization + T ----
    // Each thread owns float4 #tid of each vector (256 float4 per vector).
    float4 raw[NREF];
    float ss[NREF];
#pragma unroll
    for (int k = 0; k < NREF; k++) {
        raw[k] = ((const float4*)(vecs + k * FEAT))[tid];
        ss[k] = raw[k].x * raw[k].x + raw[k].y * raw[k].y
              + raw[k].z * raw[k].z + raw[k].w * raw[k].w;
    }
#pragma unroll
    for (int o = 16; o; o >>= 1)
#pragma unroll
        for (int k = 0; k < NREF; k++) ss[k] += __shfl_xor_sync(0xffffffffu, ss[k], o);
    if (lane == 0)
#pragma unroll
        for (int k = 0; k < NREF; k++) s_nred[k][warp] = ss[k];
    __syncthreads();
    if (tid < NREF) {
        float tot = 0.f;
#pragma unroll
        for (int w = 0; w < WPB; w++) tot += s_nred[tid][w];
        s_inv[tid] = rsqrtf(tot);
    }
    __syncthreads();
    float4 nv[NREF];
#pragma unroll
    for (int k = 0; k < NREF; k++) {
        float inv = s_inv[k];
        nv[k] = make_float4(raw[k].x * inv, raw[k].y * inv, raw[k].z * inv, raw[k].w * inv);
        ((float4*)sv[k])[tid] = nv[k];
    }
    // Pairwise dots g[k][i] for k>i: order (1,0)(2,0)(2,1)(3,0)(3,1)(3,2)
    float gg[6];
    {
        const int ka[6] = {1, 2, 2, 3, 3, 3};
        const int ia[6] = {0, 0, 1, 0, 1, 2};
#pragma unroll
        for (int p = 0; p < 6; p++) {
            float4 a = nv[ka[p]], b = nv[ia[p]];
            gg[p] = a.x * b.x + a.y * b.y + a.z * b.z + a.w * b.w;
        }
#pragma unroll
        for (int o = 16; o; o >>= 1)
#pragma unroll
            for (int p = 0; p < 6; p++) gg[p] += __shfl_xor_sync(0xffffffffu, gg[p], o);
        if (lane == 0)
#pragma unroll
            for (int p = 0; p < 6; p++) s_gred[warp][p] = gg[p];
    }
    __syncthreads();
    if (tid == 0) {
        float G[NREF][NREF];
        const int ka[6] = {1, 2, 2, 3, 3, 3};
        const int ia[6] = {0, 0, 1, 0, 1, 2};
#pragma unroll
        for (int p = 0; p < 6; p++) {
            float s = 0.f;
#pragma unroll
            for (int w = 0; w < WPB; w++) s += s_gred[w][p];
            G[ka[p]][ia[p]] = s;
        }
        // T recursion: P_k = H_k P_{k-1} = I - W_k T_k W_kᵀ
        float T[NREF][NREF];
#pragma unroll
        for (int i = 0; i < NREF; i++)
#pragma unroll
            for (int j = 0; j < NREF; j++) T[i][j] = 0.f;
        T[0][0] = 2.f;
        for (int k = 1; k < NREF; k++) {
            for (int j = 0; j < k; j++) {
                float t = 0.f;
                for (int i = j; i < k; i++) t += G[k][i] * T[i][j];
                T[k][j] = -2.f * t;
            }
            T[k][k] = 2.f;
        }
#pragma unroll
        for (int i = 0; i < NREF; i++)
#pragma unroll
            for (int j = 0; j < NREF; j++) s_T[i * 4 + j] = T[i][j];
    }
    __syncthreads();

    // T into registers (uniform per warp, lower-triangular: 10 live values)
    float Tr[NREF][NREF];
#pragma unroll
    for (int i = 0; i < NREF; i++)
#pragma unroll
        for (int j = 0; j < NREF; j++) Tr[i][j] = s_T[i * 4 + j];

    // ---- Persistent main loop: 2 rows (one pair) per warp per iteration ----
    long long pairs = ((long long)batch + 1) >> 1;
    long long pstride = (long long)gridDim.x * WPB;
    for (long long p = (long long)blockIdx.x * WPB + warp; p < pairs; p += pstride) {
        long long rowA = 2 * p;
        long long rowB = 2 * p + 1;
        bool hasB = rowB < batch;

        const float4* xa = (const float4*)(x + rowA * (long long)FEAT);
        const float4* xb = (const float4*)(x + rowB * (long long)FEAT);
        float4 ya[8], yb[8];
#pragma unroll
        for (int j = 0; j < 8; j++) ya[j] = __ldcs(&xa[j * 32 + lane]);
        if (hasB) {
#pragma unroll
            for (int j = 0; j < 8; j++) yb[j] = __ldcs(&xb[j * 32 + lane]);
        }

        // Pass 1: d = Wᵀ y for both rows (all dots from original y)
        float dA[NREF] = {0.f, 0.f, 0.f, 0.f};
        float dB[NREF] = {0.f, 0.f, 0.f, 0.f};
#pragma unroll
        for (int j = 0; j < 8; j++) {
#pragma unroll
            for (int k = 0; k < NREF; k++) {
                float4 v = ((const float4*)sv[k])[j * 32 + lane];
                dA[k] = fmaf(ya[j].x, v.x, dA[k]);
                dA[k] = fmaf(ya[j].y, v.y, dA[k]);
                dA[k] = fmaf(ya[j].z, v.z, dA[k]);
                dA[k] = fmaf(ya[j].w, v.w, dA[k]);
                dB[k] = fmaf(yb[j].x, v.x, dB[k]);
                dB[k] = fmaf(yb[j].y, v.y, dB[k]);
                dB[k] = fmaf(yb[j].z, v.z, dB[k]);
                dB[k] = fmaf(yb[j].w, v.w, dB[k]);
            }
        }
        // Single interleaved butterfly: 8 independent reductions pipeline
#pragma unroll
        for (int o = 16; o; o >>= 1) {
#pragma unroll
            for (int k = 0; k < NREF; k++) {
                dA[k] += __shfl_xor_sync(0xffffffffu, dA[k], o);
                dB[k] += __shfl_xor_sync(0xffffffffu, dB[k], o);
            }
        }
        // e = T d (lower triangular), negated for the fma update
        float eA[NREF], eB[NREF];
#pragma unroll
        for (int i = 0; i < NREF; i++) {
            float a = 0.f, b = 0.f;
#pragma unroll
            for (int j = 0; j < NREF; j++) {
                if (j <= i) {
                    a = fmaf(Tr[i][j], dA[j], a);
                    b = fmaf(Tr[i][j], dB[j], b);
                }
            }
            eA[i] = -a;
            eB[i] = -b;
        }

        // Pass 2: y -= W e
#pragma unroll
        for (int j = 0; j < 8; j++) {
#pragma unroll
            for (int k = 0; k < NREF; k++) {
                float4 v = ((const float4*)sv[k])[j * 32 + lane];
                ya[j].x = fmaf(eA[k], v.x, ya[j].x);
                ya[j].y = fmaf(eA[k], v.y, ya[j].y);
                ya[j].z = fmaf(eA[k], v.z, ya[j].z);
                ya[j].w = fmaf(eA[k], v.w, ya[j].w);
                yb[j].x = fmaf(eB[k], v.x, yb[j].x);
                yb[j].y = fmaf(eB[k], v.y, yb[j].y);
                yb[j].z = fmaf(eB[k], v.z, yb[j].z);
                yb[j].w = fmaf(eB[k], v.w, yb[j].w);
            }
        }

        float4* oa = (float4*)(out + rowA * (long long)FEAT);
#pragma unroll
        for (int j = 0; j < 8; j++) __stcs(&oa[j * 32 + lane], ya[j]);
        if (hasB) {
            float4* ob = (float4*)(out + rowB * (long long)FEAT);
#pragma unroll
            for (int j = 0; j < 8; j++) __stcs(&ob[j * 32 + lane], yb[j]);
        }
    }
}

extern "C" void kernel_launch(void* const* d_in, const int* in_sizes, int n_in,
                              void* d_out, int out_size) {
    const float* x = (const float*)d_in[0];       // (BATCH, 1024) fp32
    const float* vectors = (const float*)d_in[1]; // (4, 1024) fp32
    float* out = (float*)d_out;
    int batch = in_sizes[0] / FEAT;

    long long pairs = ((long long)batch + 1) >> 1;
    int blocks = (int)((pairs + WPB - 1) / WPB);
    if (blocks > GRID) blocks = GRID;
    householder_wy_kernel<<<blocks, TPB>>>(x, vectors, out, batch);
}

// round 10
// speedup vs baseline: 1.7544x; 1.7544x over previous
#include <cuda_runtime.h>
#include <cuda_bf16.h>

#define FEAT 1024
#define NREF 4
#define WPB 8            // warps per block
#define TPB (WPB * 32)
#define RPB (WPB * 2)    // rows per block-iteration (2 rows per warp)
#define GRID 296         // 2 CTAs/SM * 148 SMs, one wave, persistent

// Fused persistent kernel: per-block normalize prologue (cheap: 16KB from L2),
// then R7-proven body: 2 rows/warp, sequential reflections, shared v regs,
// interleaved shfl butterflies.
__global__ __launch_bounds__(TPB, 2) void householder_fused_kernel(
    const float* __restrict__ x, const float* __restrict__ vecs,
    float* __restrict__ out, int batch) {
    __shared__ float sv[NREF][FEAT];     // normalized vectors
    __shared__ float s_nred[NREF][WPB];  // per-warp norm partials
    __shared__ float s_inv[NREF];

    int tid = threadIdx.x;
    int warp = tid >> 5;
    int lane = tid & 31;

    // ---- Prologue: normalize the 4 vectors (identical work in every block;
    //      vectors are 16KB and L2-resident, so this is ~free at 296 blocks) ----
    {
        float ss[NREF];
#pragma unroll
        for (int k = 0; k < NREF; k++) {
            float4 r = ((const float4*)(vecs + k * FEAT))[tid];
            ss[k] = r.x * r.x + r.y * r.y + r.z * r.z + r.w * r.w;
        }
#pragma unroll
        for (int o = 16; o; o >>= 1)
#pragma unroll
            for (int k = 0; k < NREF; k++) ss[k] += __shfl_xor_sync(0xffffffffu, ss[k], o);
        if (lane == 0)
#pragma unroll
            for (int k = 0; k < NREF; k++) s_nred[k][warp] = ss[k];
        __syncthreads();
        if (tid < NREF) {
            float tot = 0.f;
#pragma unroll
            for (int w = 0; w < WPB; w++) tot += s_nred[tid][w];
            s_inv[tid] = rsqrtf(tot);
        }
        __syncthreads();
        // Reload raw vectors (L2 hit) and scale into SMEM — avoids holding
        // 16 extra registers live across the reduction.
#pragma unroll
        for (int k = 0; k < NREF; k++) {
            float4 r = ((const float4*)(vecs + k * FEAT))[tid];
            float inv = s_inv[k];
            ((float4*)sv[k])[tid] = make_float4(r.x * inv, r.y * inv, r.z * inv, r.w * inv);
        }
        __syncthreads();
    }

    // ---- Persistent main loop: each block-iteration covers 16 contiguous rows;
    //      warp handles rows (base+warp) and (base+warp+8). ----
    long long nchunks = ((long long)batch + RPB - 1) / RPB;
    for (long long c = blockIdx.x; c < nchunks; c += gridDim.x) {
        long long base = c * RPB;
        long long rowA = base + warp;
        long long rowB = rowA + WPB;
        bool hasA = rowA < batch;
        bool hasB = rowB < batch;

        const float4* xa = (const float4*)(x + rowA * (long long)FEAT);
        const float4* xb = (const float4*)(x + rowB * (long long)FEAT);
        float4 ya[8], yb[8];
        if (hasA) {
#pragma unroll
            for (int j = 0; j < 8; j++) ya[j] = __ldcs(&xa[j * 32 + lane]);
        }
        if (hasB) {
#pragma unroll
            for (int j = 0; j < 8; j++) yb[j] = __ldcs(&xb[j * 32 + lane]);
        }

#pragma unroll
        for (int k = 0; k < NREF; k++) {
            const float4* vp = (const float4*)sv[k];
            float4 vv[8];
            float da = 0.f, db = 0.f;
#pragma unroll
            for (int j = 0; j < 8; j++) {
                vv[j] = vp[j * 32 + lane];
                da = fmaf(ya[j].x, vv[j].x, da);
                da = fmaf(ya[j].y, vv[j].y, da);
                da = fmaf(ya[j].z, vv[j].z, da);
                da = fmaf(ya[j].w, vv[j].w, da);
                db = fmaf(yb[j].x, vv[j].x, db);
                db = fmaf(yb[j].y, vv[j].y, db);
                db = fmaf(yb[j].z, vv[j].z, db);
                db = fmaf(yb[j].w, vv[j].w, db);
            }
            // Two independent butterflies, interleaved so latencies overlap.
#pragma unroll
            for (int o = 16; o; o >>= 1) {
                da += __shfl_xor_sync(0xffffffffu, da, o);
                db += __shfl_xor_sync(0xffffffffu, db, o);
            }
            float sa = -2.f * da;
            float sb = -2.f * db;
#pragma unroll
            for (int j = 0; j < 8; j++) {
                ya[j].x = fmaf(sa, vv[j].x, ya[j].x);
                ya[j].y = fmaf(sa, vv[j].y, ya[j].y);
                ya[j].z = fmaf(sa, vv[j].z, ya[j].z);
                ya[j].w = fmaf(sa, vv[j].w, ya[j].w);
                yb[j].x = fmaf(sb, vv[j].x, yb[j].x);
                yb[j].y = fmaf(sb, vv[j].y, yb[j].y);
                yb[j].z = fmaf(sb, vv[j].z, yb[j].z);
                yb[j].w = fmaf(sb, vv[j].w, yb[j].w);
            }
        }

        if (hasA) {
            float4* oa = (float4*)(out + rowA * (long long)FEAT);
#pragma unroll
            for (int j = 0; j < 8; j++) __stcs(&oa[j * 32 + lane], ya[j]);
        }
        if (hasB) {
            float4* ob = (float4*)(out + rowB * (long long)FEAT);
#pragma unroll
            for (int j = 0; j < 8; j++) __stcs(&ob[j * 32 + lane], yb[j]);
        }
    }
}

extern "C" void kernel_launch(void* const* d_in, const int* in_sizes, int n_in,
                              void* d_out, int out_size) {
    const float* x = (const float*)d_in[0];       // (BATCH, 1024) fp32
    const float* vectors = (const float*)d_in[1]; // (4, 1024) fp32
    float* out = (float*)d_out;
    int batch = in_sizes[0] / FEAT;

    long long nchunks = ((long long)batch + RPB - 1) / RPB;
    int blocks = (int)(nchunks < GRID ? nchunks : GRID);
    householder_fused_kernel<<<blocks, TPB>>>(x, vectors, out, batch);
}

// round 11
// speedup vs baseline: 1.9670x; 1.1212x over previous
#include <cuda_runtime.h>
#include <cuda_bf16.h>

#define FEAT 1024
#define NREF 4
#define WPB 8            // warps per block
#define TPB (WPB * 32)
#define ROWS_PER_BLOCK (WPB * 2)

// Single fused kernel. Key identity: y - 2(v_hat.y)v_hat = y - (2/||v||^2)(v.y)v,
// so blocks stage RAW vectors into SMEM (same 16KB L2 read as before) and fold
// normalization into the per-reflection scalar. No separate normalize kernel,
// no extra memory traffic, one graph node.
__global__ __launch_bounds__(TPB, 2) void householder_apply_kernel(
    const float* __restrict__ x, const float* __restrict__ vecs,
    float* __restrict__ out, int batch) {
    __shared__ float sv[NREF][FEAT];     // raw (unnormalized) vectors
    __shared__ float s_nred[NREF][WPB];  // per-warp ||v||^2 partials
    __shared__ float s_scale[NREF];      // -2 / ||v||^2

    int tid = threadIdx.x;
    int warp = tid >> 5;
    int lane = tid & 31;

    // ---- Stage vectors to SMEM and compute -2/||v||^2 in the same pass ----
    {
        float ss[NREF];
#pragma unroll
        for (int k = 0; k < NREF; k++) {
            float4 r = ((const float4*)(vecs + k * FEAT))[tid];  // 256 f4/vector, tid in [0,256)
            ((float4*)sv[k])[tid] = r;
            ss[k] = r.x * r.x + r.y * r.y + r.z * r.z + r.w * r.w;
        }
#pragma unroll
        for (int o = 16; o; o >>= 1)
#pragma unroll
            for (int k = 0; k < NREF; k++) ss[k] += __shfl_xor_sync(0xffffffffu, ss[k], o);
        if (lane == 0)
#pragma unroll
            for (int k = 0; k < NREF; k++) s_nred[k][warp] = ss[k];
        __syncthreads();
        if (tid < NREF) {
            float tot = 0.f;
#pragma unroll
            for (int w = 0; w < WPB; w++) tot += s_nred[tid][w];
            s_scale[tid] = -2.f / tot;
        }
        __syncthreads();
    }

    float scale[NREF];
#pragma unroll
    for (int k = 0; k < NREF; k++) scale[k] = s_scale[k];

    // ---- R7-proven body: 2 rows per warp, sequential reflections,
    //      v registers shared across rows, interleaved butterflies ----
    long long rowA = (long long)blockIdx.x * ROWS_PER_BLOCK + warp;
    long long rowB = rowA + WPB;
    bool hasA = rowA < batch;
    bool hasB = rowB < batch;

    const float4* xa = (const float4*)(x + rowA * (long long)FEAT);
    const float4* xb = (const float4*)(x + rowB * (long long)FEAT);
    float4 ya[8], yb[8];
    if (hasA) {
#pragma unroll
        for (int j = 0; j < 8; j++) ya[j] = __ldcs(&xa[j * 32 + lane]);
    }
    if (hasB) {
#pragma unroll
        for (int j = 0; j < 8; j++) yb[j] = __ldcs(&xb[j * 32 + lane]);
    }

#pragma unroll
    for (int k = 0; k < NREF; k++) {
        const float4* vp = (const float4*)sv[k];
        float4 vv[8];
        float da = 0.f, db = 0.f;
#pragma unroll
        for (int j = 0; j < 8; j++) {
            vv[j] = vp[j * 32 + lane];
            da = fmaf(ya[j].x, vv[j].x, da);
            da = fmaf(ya[j].y, vv[j].y, da);
            da = fmaf(ya[j].z, vv[j].z, da);
            da = fmaf(ya[j].w, vv[j].w, da);
            db = fmaf(yb[j].x, vv[j].x, db);
            db = fmaf(yb[j].y, vv[j].y, db);
            db = fmaf(yb[j].z, vv[j].z, db);
            db = fmaf(yb[j].w, vv[j].w, db);
        }
        // Two independent butterflies, interleaved so latencies overlap.
#pragma unroll
        for (int o = 16; o; o >>= 1) {
            da += __shfl_xor_sync(0xffffffffu, da, o);
            db += __shfl_xor_sync(0xffffffffu, db, o);
        }
        float sa = scale[k] * da;
        float sb = scale[k] * db;
#pragma unroll
        for (int j = 0; j < 8; j++) {
            ya[j].x = fmaf(sa, vv[j].x, ya[j].x);
            ya[j].y = fmaf(sa, vv[j].y, ya[j].y);
            ya[j].z = fmaf(sa, vv[j].z, ya[j].z);
            ya[j].w = fmaf(sa, vv[j].w, ya[j].w);
            yb[j].x = fmaf(sb, vv[j].x, yb[j].x);
            yb[j].y = fmaf(sb, vv[j].y, yb[j].y);
            yb[j].z = fmaf(sb, vv[j].z, yb[j].z);
            yb[j].w = fmaf(sb, vv[j].w, yb[j].w);
        }
    }

    if (hasA) {
        float4* oa = (float4*)(out + rowA * (long long)FEAT);
#pragma unroll
        for (int j = 0; j < 8; j++) __stcs(&oa[j * 32 + lane], ya[j]);
    }
    if (hasB) {
        float4* ob = (float4*)(out + rowB * (long long)FEAT);
#pragma unroll
        for (int j = 0; j < 8; j++) __stcs(&ob[j * 32 + lane], yb[j]);
    }
}

extern "C" void kernel_launch(void* const* d_in, const int* in_sizes, int n_in,
                              void* d_out, int out_size) {
    const float* x = (const float*)d_in[0];       // (BATCH, 1024) fp32
    const float* vectors = (const float*)d_in[1]; // (4, 1024) fp32
    float* out = (float*)d_out;
    int batch = in_sizes[0] / FEAT;

    int blocks = (batch + ROWS_PER_BLOCK - 1) / ROWS_PER_BLOCK;
    householder_apply_kernel<<<blocks, TPB>>>(x, vectors, out, batch);
}